// round 12
// baseline (speedup 1.0000x reference)
#include <cuda_runtime.h>

typedef unsigned long long u64;

#define NITER 31
#define BLOCK 256

__device__ double   g_sum   = 0.0;
__device__ unsigned g_count = 0;

__device__ __forceinline__ u64 pk2(float a, float b) {
    u64 r; asm("mov.b64 %0, {%1, %2};" : "=l"(r) : "f"(a), "f"(b)); return r;
}
__device__ __forceinline__ void up2(u64 v, float &a, float &b) {
    asm("mov.b64 {%0, %1}, %2;" : "=f"(a), "=f"(b) : "l"(v));
}
__device__ __forceinline__ u64 ffma2(u64 a, u64 b, u64 c) {
    u64 d; asm("fma.rn.f32x2 %0, %1, %2, %3;" : "=l"(d) : "l"(a), "l"(b), "l"(c)); return d;
}
__device__ __forceinline__ u64 fmul2(u64 a, u64 b) {
    u64 d; asm("mul.rn.f32x2 %0, %1, %2;" : "=l"(d) : "l"(a), "l"(b)); return d;
}
__device__ __forceinline__ u64 fsub2(u64 a, u64 b) {
    u64 d; asm("sub.rn.f32x2 %0, %1, %2;" : "=l"(d) : "l"(a), "l"(b)); return d;
}
__device__ __forceinline__ u64 fadd2(u64 a, u64 b) {
    u64 d; asm("add.rn.f32x2 %0, %1, %2;" : "=l"(d) : "l"(a), "l"(b)); return d;
}
__device__ __forceinline__ float frcp_(float x) {
    float r; asm("rcp.approx.f32 %0, %1;" : "=f"(r) : "f"(x)); return r;
}
// Packed reciprocal on the two 32-bit halves (register-pair aliasing; the
// mov.b64 split/join typically compiles to nothing).
__device__ __forceinline__ u64 frcp2(u64 x) {
    float a, b; up2(x, a, b);
    return pk2(frcp_(a), frcp_(b));
}
// Common exact power-of-two renorm scale from m's exponent (pure u64 int ops).
__device__ __forceinline__ u64 exp_scale(u64 m) {
    return 0x7F0000007F000000ULL - (m & 0x7F8000007F800000ULL);
}

// Per-ray quadratic setup (|V_local| = 1, rotation invariance; only col 0 of R):
//   A = -c(1 - vlx^2),  B = vlx + 2c(plx*vlx - (P-T).V),
//   C = plx + c(plx^2 - |P-T|^2),  D = B^2 - 4AC.
struct RayQ { float D, s, i4; };   // s0 = B, i4 = 1/(4A)

__device__ __forceinline__ RayQ setup_ray(
    float px, float py, float pz, float wx, float wy, float wz,
    float r00, float r10, float r20, float tx, float ty, float tz,
    float c, float mc, float twoc)
{
    float qx = px - tx, qy = py - ty, qz = pz - tz;
    float plx  = qx*r00 + qy*r10 + qz*r20;
    float vlx  = wx*r00 + wy*r10 + wz*r20;
    float ndot = fmaf(-qx, wx, fmaf(-qy, wy, -qz*wz));   // -(P-T).V
    float nn2  = fmaf(-qx, qx, fmaf(-qy, qy, -qz*qz));   // -|P-T|^2
    float A  = fmaf(vlx*vlx, c, mc);            // -c(1-vlx^2)
    float B  = fmaf(twoc, fmaf(plx, vlx, ndot), vlx);
    float C  = fmaf(c, fmaf(plx, plx, nn2), plx);
    if (A == 0.0f) { A = 1.0f; B = 1.0f; C = 0.0f; }     // degenerate guard
    RayQ o;
    o.D  = fmaf(A * C, -4.0f, B * B);           // D = B^2 - 4AC
    o.s  = B;
    o.i4 = frcp_(4.0f * A);
    return o;
}

__global__ void __launch_bounds__(BLOCK)
lm_kernel(const float* __restrict__ P, const float* __restrict__ V,
          const float* __restrict__ R, const float* __restrict__ T,
          const float* __restrict__ Cs, const float* __restrict__ loss_in,
          float* __restrict__ out, int n, double invN)
{
    const int g = blockIdx.x * BLOCK + threadIdx.x;   // 8 rays / thread
    const int base = g * 8;

    float ssum = 0.0f;

    if (base < n) {
        const float r00 = __ldg(R + 0), r10 = __ldg(R + 3), r20 = __ldg(R + 6);
        const float tx = __ldg(T + 0), ty = __ldg(T + 1), tz = __ldg(T + 2);
        const float c    = __ldg(Cs);
        const float mc   = -c;
        const float twoc = 2.0f * c;

        RayQ rq[8];
        if (base + 8 <= n) {
            const float4* P4 = (const float4*)P;
            const float4* V4 = (const float4*)V;
            {
                float4 a0 = P4[6*g + 0], a1 = P4[6*g + 1], a2 = P4[6*g + 2];
                float4 b0 = V4[6*g + 0], b1 = V4[6*g + 1], b2 = V4[6*g + 2];
                rq[0] = setup_ray(a0.x,a0.y,a0.z, b0.x,b0.y,b0.z, r00,r10,r20, tx,ty,tz, c,mc,twoc);
                rq[1] = setup_ray(a0.w,a1.x,a1.y, b0.w,b1.x,b1.y, r00,r10,r20, tx,ty,tz, c,mc,twoc);
                rq[2] = setup_ray(a1.z,a1.w,a2.x, b1.z,b1.w,b2.x, r00,r10,r20, tx,ty,tz, c,mc,twoc);
                rq[3] = setup_ray(a2.y,a2.z,a2.w, b2.y,b2.z,b2.w, r00,r10,r20, tx,ty,tz, c,mc,twoc);
            }
            {
                float4 a0 = P4[6*g + 3], a1 = P4[6*g + 4], a2 = P4[6*g + 5];
                float4 b0 = V4[6*g + 3], b1 = V4[6*g + 4], b2 = V4[6*g + 5];
                rq[4] = setup_ray(a0.x,a0.y,a0.z, b0.x,b0.y,b0.z, r00,r10,r20, tx,ty,tz, c,mc,twoc);
                rq[5] = setup_ray(a0.w,a1.x,a1.y, b0.w,b1.x,b1.y, r00,r10,r20, tx,ty,tz, c,mc,twoc);
                rq[6] = setup_ray(a1.z,a1.w,a2.x, b1.z,b1.w,b2.x, r00,r10,r20, tx,ty,tz, c,mc,twoc);
                rq[7] = setup_ray(a2.y,a2.z,a2.w, b2.y,b2.z,b2.w, r00,r10,r20, tx,ty,tz, c,mc,twoc);
            }
        } else {
            #pragma unroll
            for (int k = 0; k < 8; ++k) {
                int i = base + k;
                if (i < n) {
                    rq[k] = setup_ray(P[3*i],P[3*i+1],P[3*i+2],
                                      V[3*i],V[3*i+1],V[3*i+2],
                                      r00,r10,r20, tx,ty,tz, c,mc,twoc);
                } else {
                    rq[k].D = 1.0f; rq[k].s = 1.0f; rq[k].i4 = 0.25f; // F ends 0
                }
            }
        }

        const u64 TWO2 = 0x4000000040000000ULL;  // (2, 2)
        const u64 ONE2 = 0x3F8000003F800000ULL;  // (1, 1)

        // Groups 0..2: direct rcp-form (s-space, R3-validated).
        // Group 3 (rays 6,7): projective form (R7-validated) — its dense fma
        // stream overlaps the rcp groups' MUFU latency.
        u64 S0 = pk2(rq[0].s, rq[1].s), D0 = pk2(rq[0].D, rq[1].D);
        u64 S1 = pk2(rq[2].s, rq[3].s), D1 = pk2(rq[2].D, rq[3].D);
        u64 S2 = pk2(rq[4].s, rq[5].s), D2 = pk2(rq[4].D, rq[5].D);
        u64 E3 = pk2(rq[6].D + 1.0f, rq[7].D + 1.0f);
        u64 p3 = pk2(rq[6].s, rq[7].s);
        u64 m3 = ONE2;
        u64 I40 = pk2(rq[0].i4, rq[1].i4);
        u64 I41 = pk2(rq[2].i4, rq[3].i4);
        u64 I42 = pk2(rq[4].i4, rq[5].i4);
        u64 I43 = pk2(rq[6].i4, rq[7].i4);

        #pragma unroll
        for (int it = 0; it < NITER; ++it) {
            // rcp groups: s' = s + s(D - s^2)/(2s^2 + 1)
            u64 q0 = fmul2(S0, S0);
            u64 q1 = fmul2(S1, S1);
            u64 q2 = fmul2(S2, S2);
            u64 w0 = fsub2(D0, q0);
            u64 w1 = fsub2(D1, q1);
            u64 w2 = fsub2(D2, q2);
            u64 d0 = ffma2(q0, TWO2, ONE2);
            u64 d1 = ffma2(q1, TWO2, ONE2);
            u64 d2 = ffma2(q2, TWO2, ONE2);
            u64 n0 = fmul2(S0, w0);
            u64 n1 = fmul2(S1, w1);
            u64 n2 = fmul2(S2, w2);
            u64 r0 = frcp2(d0);              // MUFU x2 (xu pipe, idle so far)
            u64 r1 = frcp2(d1);
            u64 r2 = frcp2(d2);
            // projective group: p' = p(p^2+E m^2), m' = m(2p^2+m^2)
            u64 pp = fmul2(p3, p3);
            u64 mm = fmul2(m3, m3);
            u64 u3 = ffma2(E3, mm, pp);
            u64 v3 = ffma2(pp, TWO2, mm);
            p3 = fmul2(p3, u3);
            m3 = fmul2(m3, v3);
            S0 = ffma2(n0, r0, S0);
            S1 = ffma2(n1, r1, S1);
            S2 = ffma2(n2, r2, S2);
            if (it & 1) {
                u64 sc = exp_scale(m3);      // exact common power-of-two
                p3 = fmul2(p3, sc);
                m3 = fmul2(m3, sc);
            }
        }

        // Epilogue: F = (s^2 - D) / (4A); accumulate F^2
        u64 ss = 0ULL;
        {
            u64 q = fmul2(S0, S0); u64 w = fsub2(D0, q);
            u64 F = fmul2(w, I40); ss = ffma2(F, F, ss);
        }
        {
            u64 q = fmul2(S1, S1); u64 w = fsub2(D1, q);
            u64 F = fmul2(w, I41); ss = ffma2(F, F, ss);
        }
        {
            u64 q = fmul2(S2, S2); u64 w = fsub2(D2, q);
            u64 F = fmul2(w, I42); ss = ffma2(F, F, ss);
        }
        {
            u64 rm = frcp2(m3);
            u64 s  = fmul2(p3, rm);
            u64 qs = fmul2(s, s);
            u64 t  = fsub2(qs, E3);          // s^2 - D - 1
            u64 w  = fadd2(t, ONE2);         // s^2 - D
            u64 F  = fmul2(w, I43);
            ss = ffma2(F, F, ss);
        }
        float sa, sb; up2(ss, sa, sb);
        ssum = sa + sb;
    }

    // Block tree reduction (float)
    #pragma unroll
    for (int o = 16; o > 0; o >>= 1)
        ssum += __shfl_xor_sync(0xffffffffu, ssum, o);
    __shared__ float wsum[BLOCK / 32];
    if ((threadIdx.x & 31) == 0) wsum[threadIdx.x >> 5] = ssum;
    __syncthreads();

    // Global double accumulation + last-block finalize (self-resetting for
    // identical behavior on every graph replay).
    if (threadIdx.x == 0) {
        float bsum = 0.0f;
        #pragma unroll
        for (int w = 0; w < BLOCK / 32; ++w) bsum += wsum[w];
        atomicAdd(&g_sum, (double)bsum);
        __threadfence();
        unsigned old = atomicAdd(&g_count, 1u);
        if (old == gridDim.x - 1) {
            __threadfence();
            double tot = g_sum;
            out[0] = (float)((double)loss_in[0] + tot * invN);
            g_sum = 0.0;
            __threadfence();
            g_count = 0;
        }
    }
}

extern "C" void kernel_launch(void* const* d_in, const int* in_sizes, int n_in,
                              void* d_out, int out_size)
{
    const float* P       = (const float*)d_in[0];
    const float* V       = (const float*)d_in[1];
    const float* R       = (const float*)d_in[2];
    const float* T       = (const float*)d_in[3];
    const float* c       = (const float*)d_in[4];
    const float* loss_in = (const float*)d_in[5];

    const int n = in_sizes[0] / 3;                 // number of rays
    int nthreads = (n + 7) / 8;                    // 8 rays per thread
    int nblocks  = (nthreads + BLOCK - 1) / BLOCK; // 2048 for N=4.19M

    lm_kernel<<<nblocks, BLOCK>>>(P, V, R, T, c, loss_in,
                                  (float*)d_out, n, 1.0 / (double)n);
}

// round 13
// speedup vs baseline: 1.1795x; 1.1795x over previous
#include <cuda_runtime.h>

typedef unsigned long long u64;

#define NITER 31
#define BLOCK 256

__device__ double   g_sum   = 0.0;
__device__ unsigned g_count = 0;

__device__ __forceinline__ u64 pk2(float a, float b) {
    u64 r; asm("mov.b64 %0, {%1, %2};" : "=l"(r) : "f"(a), "f"(b)); return r;
}
__device__ __forceinline__ void up2(u64 v, float &a, float &b) {
    asm("mov.b64 {%0, %1}, %2;" : "=f"(a), "=f"(b) : "l"(v));
}
__device__ __forceinline__ u64 ffma2(u64 a, u64 b, u64 c) {
    u64 d; asm("fma.rn.f32x2 %0, %1, %2, %3;" : "=l"(d) : "l"(a), "l"(b), "l"(c)); return d;
}
__device__ __forceinline__ u64 fmul2(u64 a, u64 b) {
    u64 d; asm("mul.rn.f32x2 %0, %1, %2;" : "=l"(d) : "l"(a), "l"(b)); return d;
}
__device__ __forceinline__ u64 fsub2(u64 a, u64 b) {
    u64 d; asm("sub.rn.f32x2 %0, %1, %2;" : "=l"(d) : "l"(a), "l"(b)); return d;
}
__device__ __forceinline__ u64 fadd2(u64 a, u64 b) {
    u64 d; asm("add.rn.f32x2 %0, %1, %2;" : "=l"(d) : "l"(a), "l"(b)); return d;
}
__device__ __forceinline__ float frcp_(float x) {
    float r; asm("rcp.approx.f32 %0, %1;" : "=f"(r) : "f"(x)); return r;
}
// sc halves = 2^(127 - exp(q_half)) — pure u64 integer arithmetic (alu pipe),
// exact power of two. No cross-half borrow for our bounded q (exp < 254).
__device__ __forceinline__ u64 exp_scale(u64 q) {
    return 0x7F0000007F000000ULL - (q & 0x7F8000007F800000ULL);
}
// Renormalize positive-normal q to [1,2) per half by forcing its exponent
// field to 127. Bit-identical to fmul2(q, exp_scale(q)) for q > 0 normal,
// but costs only integer LOP ops on the alu pipe instead of an fma-pipe mul.
__device__ __forceinline__ u64 set_exp1(u64 q) {
    return (q & 0x807FFFFF807FFFFFULL) | 0x3F8000003F800000ULL;
}

// Per-ray quadratic setup (|V_local| = 1, rotation invariance; only col 0 of R):
//   A = -c(1 - vlx^2),  B = vlx + 2c(plx*vlx - (P-T).V),
//   C = plx + c(plx^2 - |P-T|^2),  D = B^2 - 4AC.
struct RayQ { float E, s, i4; };   // E = D+1, s0 = B, i4 = 1/(4A)

__device__ __forceinline__ RayQ setup_ray(
    float px, float py, float pz, float wx, float wy, float wz,
    float r00, float r10, float r20, float tx, float ty, float tz,
    float c, float mc, float twoc)
{
    float qx = px - tx, qy = py - ty, qz = pz - tz;
    float plx  = qx*r00 + qy*r10 + qz*r20;
    float vlx  = wx*r00 + wy*r10 + wz*r20;
    float ndot = fmaf(-qx, wx, fmaf(-qy, wy, -qz*wz));   // -(P-T).V
    float nn2  = fmaf(-qx, qx, fmaf(-qy, qy, -qz*qz));   // -|P-T|^2
    float A  = fmaf(vlx*vlx, c, mc);            // -c(1-vlx^2)
    float B  = fmaf(twoc, fmaf(plx, vlx, ndot), vlx);
    float C  = fmaf(c, fmaf(plx, plx, nn2), plx);
    if (A == 0.0f) { A = 1.0f; B = 1.0f; C = 0.0f; }     // degenerate guard
    RayQ o;
    float D = fmaf(A * C, -4.0f, B * B);        // D = B^2 - 4AC
    o.E  = D + 1.0f;
    o.s  = B;
    o.i4 = frcp_(4.0f * A);
    return o;
}

__global__ void __launch_bounds__(BLOCK)
lm_kernel(const float* __restrict__ P, const float* __restrict__ V,
          const float* __restrict__ R, const float* __restrict__ T,
          const float* __restrict__ Cs, const float* __restrict__ loss_in,
          float* __restrict__ out, int n, double invN)
{
    const int g = blockIdx.x * BLOCK + threadIdx.x;   // 8 rays / thread
    const int base = g * 8;

    float ssum = 0.0f;

    if (base < n) {
        const float r00 = __ldg(R + 0), r10 = __ldg(R + 3), r20 = __ldg(R + 6);
        const float tx = __ldg(T + 0), ty = __ldg(T + 1), tz = __ldg(T + 2);
        const float c    = __ldg(Cs);
        const float mc   = -c;
        const float twoc = 2.0f * c;

        RayQ rq[8];
        if (base + 8 <= n) {
            const float4* P4 = (const float4*)P;
            const float4* V4 = (const float4*)V;
            {
                float4 a0 = P4[6*g + 0], a1 = P4[6*g + 1], a2 = P4[6*g + 2];
                float4 b0 = V4[6*g + 0], b1 = V4[6*g + 1], b2 = V4[6*g + 2];
                rq[0] = setup_ray(a0.x,a0.y,a0.z, b0.x,b0.y,b0.z, r00,r10,r20, tx,ty,tz, c,mc,twoc);
                rq[1] = setup_ray(a0.w,a1.x,a1.y, b0.w,b1.x,b1.y, r00,r10,r20, tx,ty,tz, c,mc,twoc);
                rq[2] = setup_ray(a1.z,a1.w,a2.x, b1.z,b1.w,b2.x, r00,r10,r20, tx,ty,tz, c,mc,twoc);
                rq[3] = setup_ray(a2.y,a2.z,a2.w, b2.y,b2.z,b2.w, r00,r10,r20, tx,ty,tz, c,mc,twoc);
            }
            {
                float4 a0 = P4[6*g + 3], a1 = P4[6*g + 4], a2 = P4[6*g + 5];
                float4 b0 = V4[6*g + 3], b1 = V4[6*g + 4], b2 = V4[6*g + 5];
                rq[4] = setup_ray(a0.x,a0.y,a0.z, b0.x,b0.y,b0.z, r00,r10,r20, tx,ty,tz, c,mc,twoc);
                rq[5] = setup_ray(a0.w,a1.x,a1.y, b0.w,b1.x,b1.y, r00,r10,r20, tx,ty,tz, c,mc,twoc);
                rq[6] = setup_ray(a1.z,a1.w,a2.x, b1.z,b1.w,b2.x, r00,r10,r20, tx,ty,tz, c,mc,twoc);
                rq[7] = setup_ray(a2.y,a2.z,a2.w, b2.y,b2.z,b2.w, r00,r10,r20, tx,ty,tz, c,mc,twoc);
            }
        } else {
            #pragma unroll
            for (int k = 0; k < 8; ++k) {
                int i = base + k;
                if (i < n) {
                    rq[k] = setup_ray(P[3*i],P[3*i+1],P[3*i+2],
                                      V[3*i],V[3*i+1],V[3*i+2],
                                      r00,r10,r20, tx,ty,tz, c,mc,twoc);
                } else {
                    rq[k].E = 2.0f; rq[k].s = 1.0f; rq[k].i4 = 0.25f; // F ends 0
                }
            }
        }

        const u64 TWO2 = 0x4000000040000000ULL;  // (2, 2)
        const u64 ONE2 = 0x3F8000003F800000ULL;  // (1, 1)

        u64 E[4], p[4], q[4], I4[4];
        #pragma unroll
        for (int k = 0; k < 4; ++k) {
            E[k]  = pk2(rq[2*k].E,  rq[2*k+1].E);
            p[k]  = pk2(rq[2*k].s,  rq[2*k+1].s);   // s = p/q, q0 = 1
            q[k]  = ONE2;
            I4[k] = pk2(rq[2*k].i4, rq[2*k+1].i4);
        }

        // Projective LM: s' = s(s^2+E)/(2s^2+1)
        //   p' = p (p^2 + E q^2),  q' = q (2 p^2 + q^2)
        // Renorm every 2nd iteration by the exact common power of two 2^-k:
        //   q: integer exponent-set to 127 (alu pipe, bit-identical to the mul)
        //   p: fmul2 by 2^-k (handles any sign/magnitude)
        #pragma unroll
        for (int it = 0; it < NITER; ++it) {
            #pragma unroll
            for (int k = 0; k < 4; ++k) {
                u64 pp = fmul2(p[k], p[k]);
                u64 qq = fmul2(q[k], q[k]);
                u64 u  = ffma2(E[k], qq, pp);    // p^2 + E q^2
                u64 v  = ffma2(pp, TWO2, qq);    // 2 p^2 + q^2
                p[k] = fmul2(p[k], u);
                q[k] = fmul2(q[k], v);
            }
            if (it & 1) {
                #pragma unroll
                for (int k = 0; k < 4; ++k) {
                    u64 sc = exp_scale(q[k]);    // 2^-k per half (int ops)
                    p[k] = fmul2(p[k], sc);      // exact
                    q[k] = set_exp1(q[k]);       // exact, alu pipe only
                }
            }
        }

        // Epilogue: s = p/q, F = (s^2 - D) i4 = (s^2 - E + 1) i4
        u64 ss = 0ULL;
        #pragma unroll
        for (int k = 0; k < 4; ++k) {
            float qa, qb; up2(q[k], qa, qb);
            u64 rq2 = pk2(frcp_(qa), frcp_(qb));
            u64 s  = fmul2(p[k], rq2);
            u64 qs = fmul2(s, s);
            u64 t  = fsub2(qs, E[k]);            // s^2 - D - 1
            u64 w  = fadd2(t, ONE2);             // s^2 - D
            u64 F  = fmul2(w, I4[k]);
            ss = ffma2(F, F, ss);
        }
        float sa, sb; up2(ss, sa, sb);
        ssum = sa + sb;
    }

    // Block tree reduction (float)
    #pragma unroll
    for (int o = 16; o > 0; o >>= 1)
        ssum += __shfl_xor_sync(0xffffffffu, ssum, o);
    __shared__ float wsum[BLOCK / 32];
    if ((threadIdx.x & 31) == 0) wsum[threadIdx.x >> 5] = ssum;
    __syncthreads();

    // Global double accumulation + last-block finalize (self-resetting for
    // identical behavior on every graph replay).
    if (threadIdx.x == 0) {
        float bsum = 0.0f;
        #pragma unroll
        for (int w = 0; w < BLOCK / 32; ++w) bsum += wsum[w];
        atomicAdd(&g_sum, (double)bsum);
        __threadfence();
        unsigned old = atomicAdd(&g_count, 1u);
        if (old == gridDim.x - 1) {
            __threadfence();
            double tot = g_sum;
            out[0] = (float)((double)loss_in[0] + tot * invN);
            g_sum = 0.0;
            __threadfence();
            g_count = 0;
        }
    }
}

extern "C" void kernel_launch(void* const* d_in, const int* in_sizes, int n_in,
                              void* d_out, int out_size)
{
    const float* P       = (const float*)d_in[0];
    const float* V       = (const float*)d_in[1];
    const float* R       = (const float*)d_in[2];
    const float* T       = (const float*)d_in[3];
    const float* c       = (const float*)d_in[4];
    const float* loss_in = (const float*)d_in[5];

    const int n = in_sizes[0] / 3;                 // number of rays
    int nthreads = (n + 7) / 8;                    // 8 rays per thread
    int nblocks  = (nthreads + BLOCK - 1) / BLOCK; // 2048 for N=4.19M

    lm_kernel<<<nblocks, BLOCK>>>(P, V, R, T, c, loss_in,
                                  (float*)d_out, n, 1.0 / (double)n);
}